// round 11
// baseline (speedup 1.0000x reference)
#include <cuda_runtime.h>
#include <cuda_bf16.h>
#include <cstdint>

typedef unsigned long long ull;

#define Bn 12
#define Cn 64
#define Kn 32
#define Vn 32768
#define RF_OFF 0
#define SP_OFF 24576
#define ZO_OFF 417792
#define SC_OFF 25583616

__device__ __align__(16) float g_Zrec[Bn*Cn*Vn];
__device__ __align__(16) float g_P[Bn*Cn*Kn*27];
__device__ __align__(16) float g_mpad[Kn*34*34*34];
__device__ float g_msum[Kn];
__device__ float g_rf[Bn*Kn*Cn];
__device__ float g_G[Bn*Cn*Cn];
__device__ float g_cosabs[Bn*32];
__device__ float g_Dmmd[Kn];
__device__ float g_Wk[Bn*Kn];
__device__ float g_mod[Bn*Kn*Cn];
__device__ float g_M2[Cn*Cn];

__device__ __forceinline__ ull pk2(float lo, float hi){
    ull r; asm("mov.b64 %0, {%1, %2};" : "=l"(r)
               : "r"(__float_as_uint(lo)), "r"(__float_as_uint(hi)));
    return r;
}
__device__ __forceinline__ ull f2fma(ull a, ull b, ull c){
    ull d; asm("fma.rn.f32x2 %0, %1, %2, %3;" : "=l"(d) : "l"(a), "l"(b), "l"(c));
    return d;
}
__device__ __forceinline__ float wsum(float v){
    #pragma unroll
    for (int o = 16; o; o >>= 1) v += __shfl_xor_sync(0xffffffffu, v, o);
    return v;
}
__device__ __forceinline__ float wmax(float v){
    #pragma unroll
    for (int o = 16; o; o >>= 1) v = fmaxf(v, __shfl_xor_sync(0xffffffffu, v, o));
    return v;
}

__global__ void k_msum(const float* __restrict__ masks){
    int k = blockIdx.x, t = threadIdx.x;
    const float4* mp = (const float4*)(masks + (long)k*Vn);
    float s = 0.f;
    for (int i = t; i < Vn/4; i += 256){
        float4 m = __ldg(mp + i); s += m.x + m.y + m.z + m.w;
    }
    s = wsum(s);
    __shared__ float r[8];
    if ((t & 31) == 0) r[t >> 5] = s;
    __syncthreads();
    if (t == 0){
        float tot = 0.f;
        for (int i = 0; i < 8; i++) tot += r[i];
        g_msum[k] = tot;
    }
}

// padded masks: g_mpad[k][zz][yy][ww], zz/yy/ww in [0,34) = voxel-1 .. voxel+1
__global__ void k_pad(const float* __restrict__ masks){
    int k = blockIdx.x, t = threadIdx.x;
    for (int idx = t; idx < 34*34*34; idx += 256){
        int ww = idx % 34, yy = (idx/34) % 34, zz = idx / 1156;
        float v = 0.f;
        if (zz >= 1 && zz <= 32 && yy >= 1 && yy <= 32 && ww >= 1 && ww <= 32)
            v = __ldg(masks + (((long)k*32 + zz-1)*32 + yy-1)*32 + ww-1);
        g_mpad[(long)k*39304 + idx] = v;
    }
}

__global__ void k_rf(const float* __restrict__ Z, const float* __restrict__ masks,
                     float* __restrict__ out){
    int b = blockIdx.y;
    int c0 = (blockIdx.x & 15)*4, k0 = (blockIdx.x >> 4)*8, t = threadIdx.x;
    float acc[4][8];
    #pragma unroll
    for (int i = 0; i < 4; i++)
        #pragma unroll
        for (int j = 0; j < 8; j++) acc[i][j] = 0.f;
    for (int i = t; i < Vn/4; i += 256){
        float4 zv[4];
        #pragma unroll
        for (int ci = 0; ci < 4; ci++)
            zv[ci] = __ldg((const float4*)(Z + ((long)(b*Cn + c0+ci))*Vn) + i);
        #pragma unroll
        for (int ki = 0; ki < 8; ki++){
            float4 m = __ldg((const float4*)(masks + (long)(k0+ki)*Vn) + i);
            #pragma unroll
            for (int ci = 0; ci < 4; ci++){
                acc[ci][ki] = fmaf(zv[ci].x, m.x, acc[ci][ki]);
                acc[ci][ki] = fmaf(zv[ci].y, m.y, acc[ci][ki]);
                acc[ci][ki] = fmaf(zv[ci].z, m.z, acc[ci][ki]);
                acc[ci][ki] = fmaf(zv[ci].w, m.w, acc[ci][ki]);
            }
        }
    }
    __shared__ float sm[32];
    if (t < 32) sm[t] = 0.f;
    __syncthreads();
    #pragma unroll
    for (int ci = 0; ci < 4; ci++)
        #pragma unroll
        for (int ki = 0; ki < 8; ki++){
            float v = wsum(acc[ci][ki]);
            if ((t & 31) == 0) atomicAdd(&sm[ci*8+ki], v);
        }
    __syncthreads();
    if (t < 32){
        int ci = t >> 3, ki = t & 7;
        float r = sm[t] / (g_msum[k0+ki] + 1e-6f);
        int idx = (b*Kn + k0+ki)*Cn + c0+ci;
        g_rf[idx] = r;
        out[RF_OFF + idx] = r;
    }
}

__global__ void k_G(const float* __restrict__ Z){
    int b = blockIdx.y, t = threadIdx.x;
    int pi = blockIdx.x, ct1 = 0, rem = pi;
    while (rem >= 8 - ct1){ rem -= 8 - ct1; ct1++; }
    int a0 = ct1*8, b0 = (ct1 + rem)*8;
    float acc[8][8];
    #pragma unroll
    for (int i = 0; i < 8; i++)
        #pragma unroll
        for (int j = 0; j < 8; j++) acc[i][j] = 0.f;
    for (int i = t; i < Vn/4; i += 256){
        float4 za[8];
        #pragma unroll
        for (int r = 0; r < 8; r++)
            za[r] = __ldg((const float4*)(Z + ((long)(b*Cn + a0+r))*Vn) + i);
        #pragma unroll
        for (int s = 0; s < 8; s++){
            float4 zb = __ldg((const float4*)(Z + ((long)(b*Cn + b0+s))*Vn) + i);
            #pragma unroll
            for (int r = 0; r < 8; r++){
                acc[r][s] = fmaf(za[r].x, zb.x, acc[r][s]);
                acc[r][s] = fmaf(za[r].y, zb.y, acc[r][s]);
                acc[r][s] = fmaf(za[r].z, zb.z, acc[r][s]);
                acc[r][s] = fmaf(za[r].w, zb.w, acc[r][s]);
            }
        }
    }
    __shared__ float sm[64];
    if (t < 64) sm[t] = 0.f;
    __syncthreads();
    #pragma unroll
    for (int r = 0; r < 8; r++)
        #pragma unroll
        for (int s = 0; s < 8; s++){
            float v = wsum(acc[r][s]);
            if ((t & 31) == 0) atomicAdd(&sm[r*8+s], v);
        }
    __syncthreads();
    if (t < 64){
        int r = t >> 3, s = t & 7;
        float v = sm[t];
        g_G[(b*Cn + a0+r)*Cn + b0+s] = v;
        g_G[(b*Cn + b0+s)*Cn + a0+r] = v;
    }
}

__global__ void k_ortho(const float* __restrict__ sw, const float* __restrict__ nw){
    int b = blockIdx.x, o = threadIdx.x;
    const float* Gb = g_G + b*Cn*Cn;
    float swr[64], nwr[64];
    #pragma unroll
    for (int c = 0; c < 64; c++){
        swr[c] = __ldg(sw + o*64 + c);
        nwr[c] = __ldg(nw + o*64 + c);
    }
    float ss = 0.f, nn = 0.f, sn = 0.f;
    for (int c1 = 0; c1 < 64; c1++){
        float s1 = swr[c1], n1 = nwr[c1];
        #pragma unroll 8
        for (int c2 = 0; c2 < 64; c2++){
            float g  = __ldg(Gb + c1*64 + c2);
            float s2 = swr[c2] * g;
            float n2 = nwr[c2] * g;
            ss = fmaf(s1, s2, ss);
            nn = fmaf(n1, n2, nn);
            sn = fmaf(s1, n2, sn);
        }
    }
    float cs = sn / (fmaxf(sqrtf(ss), 1e-8f) * fmaxf(sqrtf(nn), 1e-8f));
    g_cosabs[b*32 + o] = fabsf(cs);
}

__global__ void k_mmd(const int* __restrict__ labels){
    int k = blockIdx.x, t = threadIdx.x;
    __shared__ float x2s[12], S[9], Dg[3];
    if (t < 9) S[t] = 0.f;
    if (t < 3) Dg[t] = 0.f;
    float ip = 0.f; int i = 0, j = 0;
    if (t < 144){
        i = t / 12; j = t % 12;
        const float* ri = g_rf + (i*Kn + k)*Cn;
        const float* rj = g_rf + (j*Kn + k)*Cn;
        for (int c = 0; c < 64; c++) ip = fmaf(__ldg(ri+c), __ldg(rj+c), ip);
        if (i == j) x2s[i] = ip;
    }
    __syncthreads();
    if (t < 144){
        float d2 = fmaxf(x2s[i] + x2s[j] - 2.f*ip, 0.f);
        float kb = 0.25f*(expf(-d2/0.02f) + expf(-d2/0.5f)
                        + expf(-d2/2.0f) + expf(-d2/8.0f));
        int ci = __ldg(labels + i), cj = __ldg(labels + j);
        atomicAdd(&S[ci*3 + cj], kb);
        if (i == j) atomicAdd(&Dg[ci], kb);
    }
    __syncthreads();
    if (t == 0){
        int pa[3] = {2, 1, 2}, pb[3] = {0, 0, 1};
        float D = 0.f;
        #pragma unroll
        for (int p = 0; p < 3; p++){
            int a = pa[p], c = pb[p];
            D += (S[a*3+a] - Dg[a])/12.f + (S[c*3+c] - Dg[c])/12.f
               - 2.f*S[a*3+c]/16.f;
        }
        g_Dmmd[k] = D;
    }
}

__global__ void k_wk(const float* __restrict__ prior, const float* __restrict__ ages,
                     float* __restrict__ out){
    int k = threadIdx.x;
    float D = g_Dmmd[k];
    float mx = fmaxf(wmax(D), 1e-6f);
    float nm = fmaxf(D / mx, 0.f);
    float pr = __ldg(prior + k);
    float pm = wmax(pr); float lp = pr - pm - logf(wsum(expf(pr - pm)));
    float qm = wmax(nm); float lq = nm - qm - logf(wsum(expf(nm - qm)));
    float p = expf(lp), q = expf(lq);
    float reg = wsum(0.5f*(q*(lq - lp) + p*(lp - lq)) / 32.f);
    float os = 0.f;
    #pragma unroll
    for (int i = 0; i < 12; i++) os += g_cosabs[i*32 + k];
    float ortho = wsum(os) / 384.f;
    if (k == 0) out[SC_OFF] = reg + ortho;
    float base = 0.7f*pr + 0.3f*nm;
    for (int b = 0; b < 12; b++){
        float af = 1.f + log1pf(expf(0.1f*(__ldg(ages + b) - 50.f)));
        float v  = fminf(fmaxf(base*af, 0.f), 2.f);
        float e  = expf(v - wmax(v));
        g_Wk[b*32 + k] = e / wsum(e);
    }
}

__global__ void k_spatial(const float* __restrict__ masks, float* __restrict__ out){
    int b = blockIdx.y, z = blockIdx.x, t = threadIdx.x;
    __shared__ float wk[32];
    if (t < 32) wk[t] = g_Wk[b*32 + t];
    __syncthreads();
    long v = (long)z*1024 + t*4;
    float4 a = make_float4(0.f, 0.f, 0.f, 0.f);
    for (int k = 0; k < 32; k++){
        float4 m = __ldg((const float4*)(masks + (long)k*Vn + v));
        float w = wk[k];
        a.x = fmaf(w, m.x, a.x); a.y = fmaf(w, m.y, a.y);
        a.z = fmaf(w, m.z, a.z); a.w = fmaf(w, m.w, a.w);
    }
    *((float4*)(out + SP_OFF + (long)b*Vn + v)) = a;
}

__global__ void k_mod(const float* __restrict__ w1, const float* __restrict__ b1,
                      const float* __restrict__ w2, const float* __restrict__ b2){
    int k = blockIdx.x, b = blockIdx.y, t = threadIdx.x;
    __shared__ float hs[16];
    const float* rf = g_rf + (b*Kn + k)*Cn;
    if (t < 16){
        float a = __ldg(b1 + t);
        for (int c = 0; c < 64; c++) a = fmaf(__ldg(rf + c), __ldg(w1 + t*64 + c), a);
        hs[t] = fmaxf(a, 0.f);
    }
    __syncthreads();
    float a = __ldg(b2 + t);
    #pragma unroll
    for (int r = 0; r < 16; r++) a = fmaf(hs[r], __ldg(w2 + t*16 + r), a);
    g_mod[(b*Kn + k)*Cn + t] = (a > 20.f) ? a : log1pf(expf(a));
}

__global__ void k_m2(const float* __restrict__ up, const float* __restrict__ sw){
    int idx = blockIdx.x*256 + threadIdx.x;
    if (idx >= 4096) return;
    int o = idx >> 6, c = idx & 63;
    float a = 0.f;
    for (int m = 0; m < 32; m++) a = fmaf(__ldg(up + o*32 + m), __ldg(sw + m*64 + c), a);
    g_M2[idx] = a;
}

__global__ void k_P(const float* __restrict__ rw){
    long idx = (long)blockIdx.x*256 + threadIdx.x;
    if (idx >= (long)Bn*Cn*Kn*27) return;
    int d = idx % 27;
    int k = (idx / 27) % 32;
    int o = (idx / 864) % 64;
    int b = (int)(idx / 55296);
    const float* rf = g_rf + (b*Kn + k)*Cn;
    float a = 0.f;
    for (int i = 0; i < 64; i++)
        a = fmaf(__ldg(rw + (long)(o*64 + i)*27 + d), __ldg(rf + i), a);
    g_P[idx] = a;
}

__global__ void __launch_bounds__(128)
k_conv(){
    __shared__ float Ps[8*32*27];
    int ot = blockIdx.x, b = blockIdx.y, z = blockIdx.z;
    int t = threadIdx.x;
    int o0 = ot*8;
    for (int idx = t; idx < 6912; idx += 128)
        Ps[idx] = g_P[(long)(b*Cn + o0)*864 + idx];
    __syncthreads();
    int y = t >> 2, w0 = (t & 3)*8;
    ull acc[8][4];
    #pragma unroll
    for (int o = 0; o < 8; o++)
        #pragma unroll
        for (int vp = 0; vp < 4; vp++) acc[o][vp] = 0ull;
    for (int k = 0; k < 32; k++){
        #pragma unroll
        for (int dzy = 0; dzy < 9; dzy++){
            int dz = dzy/3, dy = dzy%3;
            const float* mb = g_mpad + (((long)k*34 + z+dz)*34 + y+dy)*34 + w0;
            float m[10];
            #pragma unroll
            for (int jj = 0; jj < 10; jj++) m[jj] = __ldg(mb + jj);
            ull pr[9];
            #pragma unroll
            for (int jj = 0; jj < 9; jj++) pr[jj] = pk2(m[jj], m[jj+1]);
            #pragma unroll
            for (int dx = 0; dx < 3; dx++){
                #pragma unroll
                for (int o = 0; o < 8; o++){
                    float pf = Ps[(o*32 + k)*27 + dzy*3 + dx];
                    ull pp = pk2(pf, pf);
                    #pragma unroll
                    for (int vp = 0; vp < 4; vp++)
                        acc[o][vp] = f2fma(pp, pr[2*vp + dx], acc[o][vp]);
                }
            }
        }
    }
    long vox = (long)z*1024 + y*32 + w0;
    #pragma unroll
    for (int o = 0; o < 8; o++){
        long off = ((long)(b*Cn + o0 + o))*Vn + vox;
        #pragma unroll
        for (int vp = 0; vp < 4; vp++)
            *((ull*)(g_Zrec + off + 2*vp)) = acc[o][vp];
    }
}

__global__ void __launch_bounds__(256)
k_final(const float* __restrict__ Z, const float* __restrict__ masks,
        float* __restrict__ out){
    __shared__ float M2s[16*64], modsm[32*16];
    int chunk = blockIdx.x, o0 = blockIdx.y*16, b = blockIdx.z;
    int t = threadIdx.x;
    for (int idx = t; idx < 1024; idx += 256){
        int i = idx >> 6, c = idx & 63;
        M2s[idx] = g_M2[(o0+i)*64 + c];
    }
    for (int idx = t; idx < 512; idx += 256){
        int k = idx >> 4, i = idx & 15;
        modsm[idx] = g_mod[(b*Kn + k)*Cn + o0 + i];
    }
    __syncthreads();
    long v = (long)chunk*256 + t;
    float acc[16], mac[16];
    #pragma unroll
    for (int i = 0; i < 16; i++){ acc[i] = 0.f; mac[i] = 0.f; }
    for (int c = 0; c < 64; c++){
        float zv = __ldg(Z + ((long)(b*Cn + c))*Vn + v);
        #pragma unroll
        for (int i = 0; i < 16; i++) acc[i] = fmaf(M2s[i*64 + c], zv, acc[i]);
    }
    for (int k = 0; k < 32; k++){
        float mv = __ldg(masks + (long)k*Vn + v);
        #pragma unroll
        for (int i = 0; i < 16; i++) mac[i] = fmaf(modsm[k*16 + i], mv, mac[i]);
    }
    float sp = out[SP_OFF + (long)b*Vn + v];
    #pragma unroll
    for (int i = 0; i < 16; i++){
        float zr = g_Zrec[((long)(b*Cn + o0 + i))*Vn + v];
        out[ZO_OFF + ((long)(b*Cn + o0 + i))*Vn + v]
            = acc[i] + 0.1f * (zr * mac[i] * sp);
    }
}

extern "C" void kernel_launch(void* const* d_in, const int* in_sizes, int n_in,
                              void* d_out, int out_size) {
    const float* Z      = (const float*)d_in[0];
    const float* masks  = (const float*)d_in[1];
    const int*   labels = (const int*)d_in[2];
    const float* ages   = (const float*)d_in[3];
    const float* prior  = (const float*)d_in[4];
    const float* sw     = (const float*)d_in[5];
    const float* nw     = (const float*)d_in[6];
    const float* up     = (const float*)d_in[7];
    const float* rw     = (const float*)d_in[8];
    const float* w1     = (const float*)d_in[9];
    const float* b1     = (const float*)d_in[10];
    const float* w2     = (const float*)d_in[11];
    const float* b2     = (const float*)d_in[12];
    float* out = (float*)d_out;

    k_msum   <<<32, 256>>>(masks);
    k_pad    <<<32, 256>>>(masks);
    k_rf     <<<dim3(64, 12), 256>>>(Z, masks, out);
    k_G      <<<dim3(36, 12), 256>>>(Z);
    k_ortho  <<<12, 32>>>(sw, nw);
    k_mmd    <<<32, 160>>>(labels);
    k_wk     <<<1, 32>>>(prior, ages, out);
    k_spatial<<<dim3(32, 12), 256>>>(masks, out);
    k_mod    <<<dim3(32, 12), 64>>>(w1, b1, w2, b2);
    k_m2     <<<16, 256>>>(up, sw);
    k_P      <<<2592, 256>>>(rw);
    k_conv   <<<dim3(8, 12, 32), 128>>>();
    k_final  <<<dim3(128, 4, 12), 256>>>(Z, masks, out);
}

// round 14
// speedup vs baseline: 1.3167x; 1.3167x over previous
#include <cuda_runtime.h>
#include <cuda_bf16.h>
#include <cstdint>

typedef unsigned long long ull;

#define Bn 12
#define Cn 64
#define Kn 32
#define Vn 32768
#define RF_OFF 0
#define SP_OFF 24576
#define ZO_OFF 417792
#define SC_OFF 25583616
#define SSTR 72

__device__ __align__(16) float g_Zrec[Bn*Cn*Vn];
__device__ __align__(16) float g_P[Bn*Cn*Kn*27];
__device__ __align__(16) float g_mpad[Kn*34*34*34];
__device__ __align__(16) __nv_bfloat16 g_Mb[(long)Vn*896];
__device__ __align__(16) __nv_bfloat16 g_Phi[768*896];
__device__ __align__(16) __nv_bfloat16 g_Plo[768*896];
__device__ float g_msum[Kn];
__device__ float g_rf[Bn*Kn*Cn];
__device__ float g_G[Bn*Cn*Cn];
__device__ float g_cosabs[Bn*32];
__device__ float g_Dmmd[Kn];
__device__ float g_Wk[Bn*Kn];
__device__ float g_mod[Bn*Kn*Cn];
__device__ float g_M2[Cn*Cn];

__device__ __forceinline__ float wsum(float v){
    #pragma unroll
    for (int o = 16; o; o >>= 1) v += __shfl_xor_sync(0xffffffffu, v, o);
    return v;
}
__device__ __forceinline__ float wmax(float v){
    #pragma unroll
    for (int o = 16; o; o >>= 1) v = fmaxf(v, __shfl_xor_sync(0xffffffffu, v, o));
    return v;
}
__device__ __forceinline__ uint32_t s2u(const void* p){
    uint32_t a;
    asm("{ .reg .u64 t; cvta.to.shared.u64 t, %1; cvt.u32.u64 %0, t; }"
        : "=r"(a) : "l"(p));
    return a;
}
__device__ __forceinline__ void ldsm_x4(uint32_t* r, uint32_t addr){
    asm volatile("ldmatrix.sync.aligned.m8n8.x4.shared.b16 {%0,%1,%2,%3}, [%4];"
                 : "=r"(r[0]), "=r"(r[1]), "=r"(r[2]), "=r"(r[3]) : "r"(addr));
}
__device__ __forceinline__ void ldsm_x2(uint32_t* r, uint32_t addr){
    asm volatile("ldmatrix.sync.aligned.m8n8.x2.shared.b16 {%0,%1}, [%2];"
                 : "=r"(r[0]), "=r"(r[1]) : "r"(addr));
}
__device__ __forceinline__ void mma16816(float* c, const uint32_t* a, const uint32_t* b){
    asm volatile("mma.sync.aligned.m16n8k16.row.col.f32.bf16.bf16.f32 "
        "{%0,%1,%2,%3}, {%4,%5,%6,%7}, {%8,%9}, {%0,%1,%2,%3};"
        : "+f"(c[0]), "+f"(c[1]), "+f"(c[2]), "+f"(c[3])
        : "r"(a[0]), "r"(a[1]), "r"(a[2]), "r"(a[3]), "r"(b[0]), "r"(b[1]));
}

__global__ void k_msum(const float* __restrict__ masks){
    int k = blockIdx.x, t = threadIdx.x;
    const float4* mp = (const float4*)(masks + (long)k*Vn);
    float s = 0.f;
    for (int i = t; i < Vn/4; i += 256){
        float4 m = __ldg(mp + i); s += m.x + m.y + m.z + m.w;
    }
    s = wsum(s);
    __shared__ float r[8];
    if ((t & 31) == 0) r[t >> 5] = s;
    __syncthreads();
    if (t == 0){
        float tot = 0.f;
        for (int i = 0; i < 8; i++) tot += r[i];
        g_msum[k] = tot;
    }
}

__global__ void k_pad(const float* __restrict__ masks){
    int k = blockIdx.x, t = threadIdx.x;
    for (int idx = t; idx < 34*34*34; idx += 256){
        int ww = idx % 34, yy = (idx/34) % 34, zz = idx / 1156;
        float v = 0.f;
        if (zz >= 1 && zz <= 32 && yy >= 1 && yy <= 32 && ww >= 1 && ww <= 32)
            v = __ldg(masks + (((long)k*32 + zz-1)*32 + yy-1)*32 + ww-1);
        g_mpad[(long)k*39304 + idx] = v;
    }
}

__global__ void k_rf(const float* __restrict__ Z, const float* __restrict__ masks,
                     float* __restrict__ out){
    int b = blockIdx.y;
    int c0 = (blockIdx.x & 15)*4, k0 = (blockIdx.x >> 4)*8, t = threadIdx.x;
    float acc[4][8];
    #pragma unroll
    for (int i = 0; i < 4; i++)
        #pragma unroll
        for (int j = 0; j < 8; j++) acc[i][j] = 0.f;
    for (int i = t; i < Vn/4; i += 256){
        float4 zv[4];
        #pragma unroll
        for (int ci = 0; ci < 4; ci++)
            zv[ci] = __ldg((const float4*)(Z + ((long)(b*Cn + c0+ci))*Vn) + i);
        #pragma unroll
        for (int ki = 0; ki < 8; ki++){
            float4 m = __ldg((const float4*)(masks + (long)(k0+ki)*Vn) + i);
            #pragma unroll
            for (int ci = 0; ci < 4; ci++){
                acc[ci][ki] = fmaf(zv[ci].x, m.x, acc[ci][ki]);
                acc[ci][ki] = fmaf(zv[ci].y, m.y, acc[ci][ki]);
                acc[ci][ki] = fmaf(zv[ci].z, m.z, acc[ci][ki]);
                acc[ci][ki] = fmaf(zv[ci].w, m.w, acc[ci][ki]);
            }
        }
    }
    __shared__ float sm[32];
    if (t < 32) sm[t] = 0.f;
    __syncthreads();
    #pragma unroll
    for (int ci = 0; ci < 4; ci++)
        #pragma unroll
        for (int ki = 0; ki < 8; ki++){
            float v = wsum(acc[ci][ki]);
            if ((t & 31) == 0) atomicAdd(&sm[ci*8+ki], v);
        }
    __syncthreads();
    if (t < 32){
        int ci = t >> 3, ki = t & 7;
        float r = sm[t] / (g_msum[k0+ki] + 1e-6f);
        int idx = (b*Kn + k0+ki)*Cn + c0+ci;
        g_rf[idx] = r;
        out[RF_OFF + idx] = r;
    }
}

__global__ void k_G(const float* __restrict__ Z){
    int b = blockIdx.y, t = threadIdx.x;
    int pi = blockIdx.x, ct1 = 0, rem = pi;
    while (rem >= 8 - ct1){ rem -= 8 - ct1; ct1++; }
    int a0 = ct1*8, b0 = (ct1 + rem)*8;
    float acc[8][8];
    #pragma unroll
    for (int i = 0; i < 8; i++)
        #pragma unroll
        for (int j = 0; j < 8; j++) acc[i][j] = 0.f;
    for (int i = t; i < Vn/4; i += 256){
        float4 za[8];
        #pragma unroll
        for (int r = 0; r < 8; r++)
            za[r] = __ldg((const float4*)(Z + ((long)(b*Cn + a0+r))*Vn) + i);
        #pragma unroll
        for (int s = 0; s < 8; s++){
            float4 zb = __ldg((const float4*)(Z + ((long)(b*Cn + b0+s))*Vn) + i);
            #pragma unroll
            for (int r = 0; r < 8; r++){
                acc[r][s] = fmaf(za[r].x, zb.x, acc[r][s]);
                acc[r][s] = fmaf(za[r].y, zb.y, acc[r][s]);
                acc[r][s] = fmaf(za[r].z, zb.z, acc[r][s]);
                acc[r][s] = fmaf(za[r].w, zb.w, acc[r][s]);
            }
        }
    }
    __shared__ float sm[64];
    if (t < 64) sm[t] = 0.f;
    __syncthreads();
    #pragma unroll
    for (int r = 0; r < 8; r++)
        #pragma unroll
        for (int s = 0; s < 8; s++){
            float v = wsum(acc[r][s]);
            if ((t & 31) == 0) atomicAdd(&sm[r*8+s], v);
        }
    __syncthreads();
    if (t < 64){
        int r = t >> 3, s = t & 7;
        float v = sm[t];
        g_G[(b*Cn + a0+r)*Cn + b0+s] = v;
        g_G[(b*Cn + b0+s)*Cn + a0+r] = v;
    }
}

__global__ void k_ortho(const float* __restrict__ sw, const float* __restrict__ nw){
    int b = blockIdx.x, o = threadIdx.x;
    const float* Gb = g_G + b*Cn*Cn;
    float swr[64], nwr[64];
    #pragma unroll
    for (int c = 0; c < 64; c++){
        swr[c] = __ldg(sw + o*64 + c);
        nwr[c] = __ldg(nw + o*64 + c);
    }
    float ss = 0.f, nn = 0.f, sn = 0.f;
    for (int c1 = 0; c1 < 64; c1++){
        float s1 = swr[c1], n1 = nwr[c1];
        #pragma unroll 8
        for (int c2 = 0; c2 < 64; c2++){
            float g  = __ldg(Gb + c1*64 + c2);
            float s2 = swr[c2] * g;
            float n2 = nwr[c2] * g;
            ss = fmaf(s1, s2, ss);
            nn = fmaf(n1, n2, nn);
            sn = fmaf(s1, n2, sn);
        }
    }
    float cs = sn / (fmaxf(sqrtf(ss), 1e-8f) * fmaxf(sqrtf(nn), 1e-8f));
    g_cosabs[b*32 + o] = fabsf(cs);
}

__global__ void k_mmd(const int* __restrict__ labels){
    int k = blockIdx.x, t = threadIdx.x;
    __shared__ float x2s[12], S[9], Dg[3];
    if (t < 9) S[t] = 0.f;
    if (t < 3) Dg[t] = 0.f;
    float ip = 0.f; int i = 0, j = 0;
    if (t < 144){
        i = t / 12; j = t % 12;
        const float* ri = g_rf + (i*Kn + k)*Cn;
        const float* rj = g_rf + (j*Kn + k)*Cn;
        for (int c = 0; c < 64; c++) ip = fmaf(__ldg(ri+c), __ldg(rj+c), ip);
        if (i == j) x2s[i] = ip;
    }
    __syncthreads();
    if (t < 144){
        float d2 = fmaxf(x2s[i] + x2s[j] - 2.f*ip, 0.f);
        float kb = 0.25f*(expf(-d2/0.02f) + expf(-d2/0.5f)
                        + expf(-d2/2.0f) + expf(-d2/8.0f));
        int ci = __ldg(labels + i), cj = __ldg(labels + j);
        atomicAdd(&S[ci*3 + cj], kb);
        if (i == j) atomicAdd(&Dg[ci], kb);
    }
    __syncthreads();
    if (t == 0){
        int pa[3] = {2, 1, 2}, pb[3] = {0, 0, 1};
        float D = 0.f;
        #pragma unroll
        for (int p = 0; p < 3; p++){
            int a = pa[p], c = pb[p];
            D += (S[a*3+a] - Dg[a])/12.f + (S[c*3+c] - Dg[c])/12.f
               - 2.f*S[a*3+c]/16.f;
        }
        g_Dmmd[k] = D;
    }
}

__global__ void k_wk(const float* __restrict__ prior, const float* __restrict__ ages,
                     float* __restrict__ out){
    int k = threadIdx.x;
    float D = g_Dmmd[k];
    float mx = fmaxf(wmax(D), 1e-6f);
    float nm = fmaxf(D / mx, 0.f);
    float pr = __ldg(prior + k);
    float pm = wmax(pr); float lp = pr - pm - logf(wsum(expf(pr - pm)));
    float qm = wmax(nm); float lq = nm - qm - logf(wsum(expf(nm - qm)));
    float p = expf(lp), q = expf(lq);
    float reg = wsum(0.5f*(q*(lq - lp) + p*(lp - lq)) / 32.f);
    float os = 0.f;
    #pragma unroll
    for (int i = 0; i < 12; i++) os += g_cosabs[i*32 + k];
    float ortho = wsum(os) / 384.f;
    if (k == 0) out[SC_OFF] = reg + ortho;
    float base = 0.7f*pr + 0.3f*nm;
    for (int b = 0; b < 12; b++){
        float af = 1.f + log1pf(expf(0.1f*(__ldg(ages + b) - 50.f)));
        float v  = fminf(fmaxf(base*af, 0.f), 2.f);
        float e  = expf(v - wmax(v));
        g_Wk[b*32 + k] = e / wsum(e);
    }
}

__global__ void k_spatial(const float* __restrict__ masks, float* __restrict__ out){
    int b = blockIdx.y, z = blockIdx.x, t = threadIdx.x;
    __shared__ float wk[32];
    if (t < 32) wk[t] = g_Wk[b*32 + t];
    __syncthreads();
    long v = (long)z*1024 + t*4;
    float4 a = make_float4(0.f, 0.f, 0.f, 0.f);
    for (int k = 0; k < 32; k++){
        float4 m = __ldg((const float4*)(masks + (long)k*Vn + v));
        float w = wk[k];
        a.x = fmaf(w, m.x, a.x); a.y = fmaf(w, m.y, a.y);
        a.z = fmaf(w, m.z, a.z); a.w = fmaf(w, m.w, a.w);
    }
    *((float4*)(out + SP_OFF + (long)b*Vn + v)) = a;
}

__global__ void k_mod(const float* __restrict__ w1, const float* __restrict__ b1,
                      const float* __restrict__ w2, const float* __restrict__ b2){
    int k = blockIdx.x, b = blockIdx.y, t = threadIdx.x;
    __shared__ float hs[16];
    const float* rf = g_rf + (b*Kn + k)*Cn;
    if (t < 16){
        float a = __ldg(b1 + t);
        for (int c = 0; c < 64; c++) a = fmaf(__ldg(rf + c), __ldg(w1 + t*64 + c), a);
        hs[t] = fmaxf(a, 0.f);
    }
    __syncthreads();
    float a = __ldg(b2 + t);
    #pragma unroll
    for (int r = 0; r < 16; r++) a = fmaf(hs[r], __ldg(w2 + t*16 + r), a);
    g_mod[(b*Kn + k)*Cn + t] = (a > 20.f) ? a : log1pf(expf(a));
}

__global__ void k_m2(const float* __restrict__ up, const float* __restrict__ sw){
    int idx = blockIdx.x*256 + threadIdx.x;
    if (idx >= 4096) return;
    int o = idx >> 6, c = idx & 63;
    float a = 0.f;
    for (int m = 0; m < 32; m++) a = fmaf(__ldg(up + o*32 + m), __ldg(sw + m*64 + c), a);
    g_M2[idx] = a;
}

__global__ void k_P(const float* __restrict__ rw){
    long idx = (long)blockIdx.x*256 + threadIdx.x;
    if (idx >= (long)Bn*Cn*Kn*27) return;
    int d = idx % 27;
    int k = (idx / 27) % 32;
    int o = (idx / 864) % 64;
    int b = (int)(idx / 55296);
    const float* rf = g_rf + (b*Kn + k)*Cn;
    float a = 0.f;
    for (int i = 0; i < 64; i++)
        a = fmaf(__ldg(rw + (long)(o*64 + i)*27 + d), __ldg(rf + i), a);
    g_P[idx] = a;
}

__global__ void k_Pbf(){
    int idx = blockIdx.x*256 + threadIdx.x;
    if (idx >= 768*896) return;
    int R = idx/896, kd = idx - R*896;
    float p = (kd < 864) ? g_P[R*864 + kd] : 0.f;
    __nv_bfloat16 hi = __float2bfloat16(p);
    float lo = p - __bfloat162float(hi);
    g_Phi[idx] = hi;
    g_Plo[idx] = __float2bfloat16(lo);
}

__global__ void k_Mb(){
    int v = blockIdx.x, t = threadIdx.x;
    int z = v >> 10, y = (v >> 5) & 31, w = v & 31;
    for (int kd = t; kd < 896; kd += 256){
        float val = 0.f;
        if (kd < 864){
            int k = kd / 27, d = kd - k*27;
            int dz = d / 9, r = d - dz*9, dy = r / 3, dx = r - dy*3;
            val = g_mpad[((long)(k*34 + z+dz)*34 + (y+dy))*34 + (w+dx)];
        }
        g_Mb[(long)v*896 + kd] = __float2bfloat16(val);
    }
}

__global__ void __launch_bounds__(256)
k_convmma(){
    __shared__ __align__(16) __nv_bfloat16 sA[128*SSTR];
    __shared__ __align__(16) __nv_bfloat16 sB[128*SSTR];
    int t = threadIdx.x, w = t >> 5, lane = t & 31;
    int vt = blockIdx.x, mt = blockIdx.y;
    long v0 = (long)vt*128;
    int mwarp = (w >> 2)*64, nwarp = (w & 3)*32;
    float acc[4][4][4];
    #pragma unroll
    for (int mi = 0; mi < 4; mi++)
        #pragma unroll
        for (int ni = 0; ni < 4; ni++)
            #pragma unroll
            for (int q = 0; q < 4; q++) acc[mi][ni][q] = 0.f;
    uint32_t aBase = s2u(sA), bBase = s2u(sB);
    int arow = lane & 15, akk = (lane >> 4) << 3;
    int brow = lane & 7,  bkk = lane & 8;
    for (int c = 0; c < 14; c++){
        for (int i = t; i < 1024; i += 256){
            int row = i >> 3, seg = i & 7;
            *((uint4*)(sB + row*SSTR + seg*8)) =
                *((const uint4*)(g_Mb + (v0+row)*896 + c*64 + seg*8));
            *((uint4*)(sA + row*SSTR + seg*8)) =
                *((const uint4*)(g_Phi + (long)(mt*128+row)*896 + c*64 + seg*8));
        }
        __syncthreads();
        #pragma unroll
        for (int ks = 0; ks < 4; ks++){
            int k0 = ks*16;
            uint32_t a[4][4], b[4][2];
            #pragma unroll
            for (int mi = 0; mi < 4; mi++)
                ldsm_x4(a[mi], aBase + ((mwarp + mi*16 + arow)*SSTR + k0 + akk)*2);
            #pragma unroll
            for (int ni = 0; ni < 4; ni++)
                ldsm_x2(b[ni], bBase + ((nwarp + ni*8 + brow)*SSTR + k0 + bkk)*2);
            #pragma unroll
            for (int mi = 0; mi < 4; mi++)
                #pragma unroll
                for (int ni = 0; ni < 4; ni++)
                    mma16816(acc[mi][ni], a[mi], b[ni]);
        }
        __syncthreads();
        for (int i = t; i < 1024; i += 256){
            int row = i >> 3, seg = i & 7;
            *((uint4*)(sA + row*SSTR + seg*8)) =
                *((const uint4*)(g_Plo + (long)(mt*128+row)*896 + c*64 + seg*8));
        }
        __syncthreads();
        #pragma unroll
        for (int ks = 0; ks < 4; ks++){
            int k0 = ks*16;
            uint32_t a[4][4], b[4][2];
            #pragma unroll
            for (int mi = 0; mi < 4; mi++)
                ldsm_x4(a[mi], aBase + ((mwarp + mi*16 + arow)*SSTR + k0 + akk)*2);
            #pragma unroll
            for (int ni = 0; ni < 4; ni++)
                ldsm_x2(b[ni], bBase + ((nwarp + ni*8 + brow)*SSTR + k0 + bkk)*2);
            #pragma unroll
            for (int mi = 0; mi < 4; mi++)
                #pragma unroll
                for (int ni = 0; ni < 4; ni++)
                    mma16816(acc[mi][ni], a[mi], b[ni]);
        }
        __syncthreads();
    }
    int trow = lane >> 2, tcol = (lane & 3)*2;
    #pragma unroll
    for (int mi = 0; mi < 4; mi++){
        int m = mt*128 + mwarp + mi*16 + trow;
        #pragma unroll
        for (int ni = 0; ni < 4; ni++){
            long off = (long)m*Vn + v0 + nwarp + ni*8 + tcol;
            float2 lo; lo.x = acc[mi][ni][0]; lo.y = acc[mi][ni][1];
            *((float2*)(g_Zrec + off)) = lo;
            float2 hi; hi.x = acc[mi][ni][2]; hi.y = acc[mi][ni][3];
            *((float2*)(g_Zrec + off + 8L*Vn)) = hi;
        }
    }
}

__global__ void __launch_bounds__(256)
k_final(const float* __restrict__ Z, const float* __restrict__ masks,
        float* __restrict__ out){
    __shared__ float M2s[32*64], modsm[32*32];
    int chunk = blockIdx.x, o0 = blockIdx.y*32, b = blockIdx.z;
    int t = threadIdx.x;
    for (int idx = t; idx < 2048; idx += 256){
        int i = idx >> 6, c = idx & 63;
        M2s[idx] = g_M2[(o0+i)*64 + c];
    }
    for (int idx = t; idx < 1024; idx += 256){
        int k = idx >> 5, i = idx & 31;
        modsm[idx] = g_mod[(b*Kn + k)*Cn + o0 + i];
    }
    __syncthreads();
    long v = (long)chunk*256 + t;
    float acc[32], mac[32];
    #pragma unroll
    for (int i = 0; i < 32; i++){ acc[i] = 0.f; mac[i] = 0.f; }
    for (int c = 0; c < 64; c++){
        float zv = __ldg(Z + ((long)(b*Cn + c))*Vn + v);
        #pragma unroll
        for (int i = 0; i < 32; i++) acc[i] = fmaf(M2s[i*64 + c], zv, acc[i]);
    }
    for (int k = 0; k < 32; k++){
        float mv = __ldg(masks + (long)k*Vn + v);
        #pragma unroll
        for (int i = 0; i < 32; i++) mac[i] = fmaf(modsm[k*32 + i], mv, mac[i]);
    }
    float sp = out[SP_OFF + (long)b*Vn + v];
    #pragma unroll
    for (int i = 0; i < 32; i++){
        float zr = g_Zrec[((long)(b*Cn + o0 + i))*Vn + v];
        out[ZO_OFF + ((long)(b*Cn + o0 + i))*Vn + v]
            = acc[i] + 0.1f * (zr * mac[i] * sp);
    }
}

extern "C" void kernel_launch(void* const* d_in, const int* in_sizes, int n_in,
                              void* d_out, int out_size) {
    const float* Z      = (const float*)d_in[0];
    const float* masks  = (const float*)d_in[1];
    const int*   labels = (const int*)d_in[2];
    const float* ages   = (const float*)d_in[3];
    const float* prior  = (const float*)d_in[4];
    const float* sw     = (const float*)d_in[5];
    const float* nw     = (const float*)d_in[6];
    const float* up     = (const float*)d_in[7];
    const float* rw     = (const float*)d_in[8];
    const float* w1     = (const float*)d_in[9];
    const float* b1     = (const float*)d_in[10];
    const float* w2     = (const float*)d_in[11];
    const float* b2     = (const float*)d_in[12];
    float* out = (float*)d_out;

    k_msum   <<<32, 256>>>(masks);
    k_pad    <<<32, 256>>>(masks);
    k_rf     <<<dim3(64, 12), 256>>>(Z, masks, out);
    k_G      <<<dim3(36, 12), 256>>>(Z);
    k_ortho  <<<12, 32>>>(sw, nw);
    k_mmd    <<<32, 160>>>(labels);
    k_wk     <<<1, 32>>>(prior, ages, out);
    k_spatial<<<dim3(32, 12), 256>>>(masks, out);
    k_mod    <<<dim3(32, 12), 64>>>(w1, b1, w2, b2);
    k_m2     <<<16, 256>>>(up, sw);
    k_P      <<<2592, 256>>>(rw);
    k_Pbf    <<<2688, 256>>>();
    k_Mb     <<<32768, 256>>>();
    k_convmma<<<dim3(256, 6), 256>>>();
    k_final  <<<dim3(128, 2, 12), 256>>>(Z, masks, out);
}